// round 2
// baseline (speedup 1.0000x reference)
#include <cuda_runtime.h>
#include <cuda_bf16.h>

#define NUM_NODES 50000
#define NUM_EDGES 600000
#define DIM 128

// ---------------- scratch (static __device__ globals; no allocation) ----------------
__device__ float g_deg[NUM_NODES];
__device__ float g_dinv[NUM_NODES];
__device__ int   g_count[NUM_NODES];
__device__ int   g_offset[NUM_NODES + 1];
__device__ int   g_cursor[NUM_NODES];
__device__ int   g_esrc[NUM_EDGES];
__device__ __align__(16) float g_ew[NUM_EDGES];
__device__ __align__(16) float g_agg[NUM_NODES * DIM];   // 25.6 MB

// ---------------- kernel 1: init ----------------
__global__ void init_kernel() {
    int i = blockIdx.x * blockDim.x + threadIdx.x;
    if (i < NUM_NODES) {
        g_deg[i] = 1.0f;     // self-loop weight
        g_count[i] = 0;
        g_cursor[i] = 0;
    }
}

// ---------------- kernel 2: degree + tgt histogram (edge_index is INT32) ----------------
__global__ void edge_pass_kernel(const int* __restrict__ eidx,
                                 const float* __restrict__ ew) {
    int e = blockIdx.x * blockDim.x + threadIdx.x;
    if (e >= NUM_EDGES) return;
    int src = eidx[e];
    int tgt = eidx[NUM_EDGES + e];
    if ((unsigned)src < NUM_NODES) atomicAdd(&g_deg[src], ew[e]);
    if ((unsigned)tgt < NUM_NODES) atomicAdd(&g_count[tgt], 1);
}

// ---------------- kernel 3: dinv ----------------
__global__ void dinv_kernel() {
    int i = blockIdx.x * blockDim.x + threadIdx.x;
    if (i < NUM_NODES) g_dinv[i] = rsqrtf(g_deg[i]);
}

// ---------------- kernel 4: single-block exclusive scan of counts -> offsets ----------------
__global__ void scan_kernel() {
    const int tid = threadIdx.x;           // 1024 threads, 4 items each -> 4096/chunk
    const int lane = tid & 31, wid = tid >> 5;
    __shared__ int warp_sums[32];
    __shared__ int s_carry;
    if (tid == 0) { s_carry = 0; g_offset[0] = 0; }
    __syncthreads();
    for (int base = 0; base < NUM_NODES; base += 4096) {
        int idx0 = base + tid * 4;
        int v[4];
#pragma unroll
        for (int j = 0; j < 4; j++) {
            int i = idx0 + j;
            v[j] = (i < NUM_NODES) ? g_count[i] : 0;
        }
        int local = v[0] + v[1] + v[2] + v[3];
        int s = local;
#pragma unroll
        for (int d = 1; d < 32; d <<= 1) {
            int t = __shfl_up_sync(0xFFFFFFFFu, s, d);
            if (lane >= d) s += t;
        }
        if (lane == 31) warp_sums[wid] = s;
        __syncthreads();
        if (wid == 0) {
            int ws = warp_sums[lane];
#pragma unroll
            for (int d = 1; d < 32; d <<= 1) {
                int t = __shfl_up_sync(0xFFFFFFFFu, ws, d);
                if (lane >= d) ws += t;
            }
            warp_sums[lane] = ws;
        }
        __syncthreads();
        int excl = (s - local) + (wid > 0 ? warp_sums[wid - 1] : 0) + s_carry;
        int run = excl;
#pragma unroll
        for (int j = 0; j < 4; j++) {
            int i = idx0 + j;
            run += v[j];
            if (i < NUM_NODES) g_offset[i + 1] = run;   // inclusive sum through i
        }
        __syncthreads();
        if (tid == 0) s_carry += warp_sums[31];
        __syncthreads();
    }
}

// ---------------- kernel 5: scatter edges into tgt-sorted order + fold normalization ----------------
__global__ void scatter_kernel(const int* __restrict__ eidx,
                               const float* __restrict__ ew) {
    int e = blockIdx.x * blockDim.x + threadIdx.x;
    if (e >= NUM_EDGES) return;
    int src = eidx[e];
    int tgt = eidx[NUM_EDGES + e];
    if ((unsigned)src >= NUM_NODES || (unsigned)tgt >= NUM_NODES) return;
    int pos = g_offset[tgt] + atomicAdd(&g_cursor[tgt], 1);
    g_esrc[pos] = src;
    g_ew[pos] = ew[e] * g_dinv[src] * g_dinv[tgt];
}

// ---------------- kernel 6: aggregation, one warp per node (atomic-free) ----------------
__global__ void agg_kernel(const float* __restrict__ x) {
    int warp_global = (blockIdx.x * blockDim.x + threadIdx.x) >> 5;
    int lane = threadIdx.x & 31;
    if (warp_global >= NUM_NODES) return;
    const int node = warp_global;
    const int beg = g_offset[node];
    const int end = g_offset[node + 1];
    const float4* __restrict__ x4 = (const float4*)x;

    float4 acc = make_float4(0.f, 0.f, 0.f, 0.f);
    for (int e = beg; e < end; e++) {
        int s = g_esrc[e];
        float w = g_ew[e];
        float4 xv = __ldg(&x4[s * 32 + lane]);
        acc.x += w * xv.x; acc.y += w * xv.y;
        acc.z += w * xv.z; acc.w += w * xv.w;
    }
    // self loop: w_norm = dinv[i]^2
    float di = g_dinv[node];
    float wl = di * di;
    float4 xv = __ldg(&x4[node * 32 + lane]);
    acc.x += wl * xv.x; acc.y += wl * xv.y;
    acc.z += wl * xv.z; acc.w += wl * xv.w;

    ((float4*)g_agg)[node * 32 + lane] = acc;
}

// ---------------- kernel 7: GEMM  out = agg @ W^T + b  ----------------
// block: 128 threads, 32-row tile. Thread t owns output column t.
__global__ void gemm_kernel(const float* __restrict__ W,
                            const float* __restrict__ b,
                            float* __restrict__ out) {
    __shared__ float4 s_tile[32 * 32];   // 32 rows x 128 cols (as float4), 16 KB
    const int row0 = blockIdx.x * 32;
    const int t = threadIdx.x;           // 0..127

    const float4* __restrict__ agg4 = (const float4*)g_agg;
    for (int idx = t; idx < 32 * 32; idx += 128) {
        int r = idx >> 5;
        int q = idx & 31;
        int row = row0 + r;
        s_tile[idx] = (row < NUM_NODES) ? agg4[row * 32 + q]
                                        : make_float4(0.f, 0.f, 0.f, 0.f);
    }
    __syncthreads();

    float acc[32];
    float bias = b[t];
#pragma unroll
    for (int r = 0; r < 32; r++) acc[r] = bias;

    const float4* __restrict__ W4 = (const float4*)W;   // W[t][k], row t per thread
    for (int q = 0; q < 32; q++) {
        float4 wv = __ldg(&W4[t * 32 + q]);
#pragma unroll
        for (int r = 0; r < 32; r++) {
            float4 a = s_tile[r * 32 + q];
            acc[r] += wv.x * a.x + wv.y * a.y + wv.z * a.z + wv.w * a.w;
        }
    }

#pragma unroll
    for (int r = 0; r < 32; r++) {
        int row = row0 + r;
        if (row < NUM_NODES) out[row * DIM + t] = acc[r];
    }
}

// ---------------- launcher ----------------
extern "C" void kernel_launch(void* const* d_in, const int* in_sizes, int n_in,
                              void* d_out, int out_size) {
    const float* x  = (const float*)d_in[0];
    const int*   ei = (const int*)d_in[1];     // edge_index: int32 (JAX x64 disabled)
    const float* ew = (const float*)d_in[2];
    const float* W  = (const float*)d_in[3];
    const float* b  = (const float*)d_in[4];
    float* out = (float*)d_out;

    (void)in_sizes; (void)n_in; (void)out_size;

    init_kernel<<<(NUM_NODES + 255) / 256, 256>>>();
    edge_pass_kernel<<<(NUM_EDGES + 255) / 256, 256>>>(ei, ew);
    dinv_kernel<<<(NUM_NODES + 255) / 256, 256>>>();
    scan_kernel<<<1, 1024>>>();
    scatter_kernel<<<(NUM_EDGES + 255) / 256, 256>>>(ei, ew);
    agg_kernel<<<(NUM_NODES * 32 + 255) / 256, 256>>>(x);
    gemm_kernel<<<(NUM_NODES + 31) / 32, 128>>>(W, b, out);
}

// round 3
// speedup vs baseline: 1.5550x; 1.5550x over previous
#include <cuda_runtime.h>
#include <cuda_bf16.h>
#include <cstdint>

#define NUM_NODES 50000
#define NUM_EDGES 600000
#define DIM 128

#define SCAN_BLK 512
#define SCAN_NB  ((NUM_NODES + SCAN_BLK - 1) / SCAN_BLK)   // 98

// ---------------- scratch (static __device__ globals; no allocation) ----------------
__device__ float g_deg[NUM_NODES];
__device__ float g_dinv[NUM_NODES];
__device__ int   g_count[NUM_NODES];
__device__ int   g_offset[NUM_NODES + 1];
__device__ int   g_cursor[NUM_NODES];
__device__ int   g_esrc[NUM_EDGES];
__device__ __align__(16) float g_ew[NUM_EDGES];
__device__ __align__(16) float g_agg[NUM_NODES * DIM];   // 25.6 MB
__device__ int   g_bsum[SCAN_NB];
__device__ int   g_bpre[SCAN_NB];

// ---------------- kernel 1: init ----------------
__global__ void init_kernel() {
    int i = blockIdx.x * blockDim.x + threadIdx.x;
    if (i < NUM_NODES) {
        g_deg[i] = 1.0f;     // self-loop weight
        g_count[i] = 0;
        g_cursor[i] = 0;
    }
}

// ---------------- kernel 2: degree + tgt histogram (edge_index is INT32) ----------------
__global__ void edge_pass_kernel(const int* __restrict__ eidx,
                                 const float* __restrict__ ew) {
    int e = blockIdx.x * blockDim.x + threadIdx.x;
    if (e >= NUM_EDGES) return;
    int src = eidx[e];
    int tgt = eidx[NUM_EDGES + e];
    if ((unsigned)src < NUM_NODES) atomicAdd(&g_deg[src], ew[e]);
    if ((unsigned)tgt < NUM_NODES) atomicAdd(&g_count[tgt], 1);
}

// ---------------- kernel 3: per-block count sums + dinv (fused) ----------------
__global__ void partial_dinv_kernel() {
    int i = blockIdx.x * SCAN_BLK + threadIdx.x;
    int lane = threadIdx.x & 31, wid = threadIdx.x >> 5;
    int c = (i < NUM_NODES) ? g_count[i] : 0;
    if (i < NUM_NODES) g_dinv[i] = rsqrtf(g_deg[i]);

    int s = c;
#pragma unroll
    for (int d = 16; d > 0; d >>= 1) s += __shfl_down_sync(0xFFFFFFFFu, s, d);
    __shared__ int ws[SCAN_BLK / 32];
    if (lane == 0) ws[wid] = s;
    __syncthreads();
    if (threadIdx.x == 0) {
        int tot = 0;
#pragma unroll
        for (int w = 0; w < SCAN_BLK / 32; w++) tot += ws[w];
        g_bsum[blockIdx.x] = tot;
    }
}

// ---------------- kernel 4: scan of 98 block sums (1 tiny block) ----------------
__global__ void bscan_kernel() {
    int t = threadIdx.x;           // 128 threads
    int lane = t & 31, wid = t >> 5;
    int v = (t < SCAN_NB) ? g_bsum[t] : 0;
    int s = v;
#pragma unroll
    for (int d = 1; d < 32; d <<= 1) {
        int tmp = __shfl_up_sync(0xFFFFFFFFu, s, d);
        if (lane >= d) s += tmp;
    }
    __shared__ int ws[4];
    if (lane == 31) ws[wid] = s;
    __syncthreads();
    if (t == 0) {
        int a = 0;
#pragma unroll
        for (int w = 0; w < 4; w++) { int tmp = ws[w]; ws[w] = a; a += tmp; }
    }
    __syncthreads();
    if (t < SCAN_NB) g_bpre[t] = s - v + ws[wid];   // exclusive prefix of block sums
}

// ---------------- kernel 5: final offsets ----------------
__global__ void offsets_kernel() {
    int i = blockIdx.x * SCAN_BLK + threadIdx.x;
    int lane = threadIdx.x & 31, wid = threadIdx.x >> 5;
    int v = (i < NUM_NODES) ? g_count[i] : 0;
    int s = v;
#pragma unroll
    for (int d = 1; d < 32; d <<= 1) {
        int tmp = __shfl_up_sync(0xFFFFFFFFu, s, d);
        if (lane >= d) s += tmp;
    }
    __shared__ int ws[SCAN_BLK / 32];
    if (lane == 31) ws[wid] = s;
    __syncthreads();
    if (wid == 0) {
        int n = (SCAN_BLK / 32);
        int wv = (lane < n) ? ws[lane] : 0;
        int t2 = wv;
#pragma unroll
        for (int d = 1; d < 32; d <<= 1) {
            int tmp = __shfl_up_sync(0xFFFFFFFFu, t2, d);
            if (lane >= d) t2 += tmp;
        }
        if (lane < n) ws[lane] = t2 - wv;   // exclusive warp prefix
    }
    __syncthreads();
    if (i < NUM_NODES) g_offset[i + 1] = g_bpre[blockIdx.x] + ws[wid] + s;
    if (i == 0) g_offset[0] = 0;
}

// ---------------- kernel 6: scatter edges into tgt-sorted order + fold normalization ----------------
__global__ void scatter_kernel(const int* __restrict__ eidx,
                               const float* __restrict__ ew) {
    int e = blockIdx.x * blockDim.x + threadIdx.x;
    if (e >= NUM_EDGES) return;
    int src = eidx[e];
    int tgt = eidx[NUM_EDGES + e];
    if ((unsigned)src >= NUM_NODES || (unsigned)tgt >= NUM_NODES) return;
    int pos = g_offset[tgt] + atomicAdd(&g_cursor[tgt], 1);
    g_esrc[pos] = src;
    g_ew[pos] = ew[e] * g_dinv[src] * g_dinv[tgt];
}

// ---------------- kernel 7: aggregation, one warp per node (atomic-free) ----------------
__global__ void agg_kernel(const float* __restrict__ x) {
    int warp_global = (blockIdx.x * blockDim.x + threadIdx.x) >> 5;
    int lane = threadIdx.x & 31;
    if (warp_global >= NUM_NODES) return;
    const int node = warp_global;
    const int beg = g_offset[node];
    const int end = g_offset[node + 1];
    const float4* __restrict__ x4 = (const float4*)x;

    float4 acc = make_float4(0.f, 0.f, 0.f, 0.f);
    for (int e = beg; e < end; e++) {
        int s = g_esrc[e];
        float w = g_ew[e];
        float4 xv = __ldg(&x4[s * 32 + lane]);
        acc.x += w * xv.x; acc.y += w * xv.y;
        acc.z += w * xv.z; acc.w += w * xv.w;
    }
    // self loop: w_norm = dinv[i]^2
    float di = g_dinv[node];
    float wl = di * di;
    float4 xv = __ldg(&x4[node * 32 + lane]);
    acc.x += wl * xv.x; acc.y += wl * xv.y;
    acc.z += wl * xv.z; acc.w += wl * xv.w;

    ((float4*)g_agg)[node * 32 + lane] = acc;
}

// ---------------- kernel 8: tf32 tensor-core GEMM  out = agg @ W^T + b ----------------
// Block 256 threads (8 warps), tile M=128 x N=128, K=128.
// Warp (wm, wn): wm = warp>>1 owns rows [wm*32, wm*32+32), wn = warp&1 owns cols [wn*64, +64).
// mma.sync.aligned.m16n8k8 tf32, fp32 accumulate.
#define SPITCH 132   // smem row pitch in words (bank-conflict-free fragment loads)

__device__ __forceinline__ uint32_t f2tf32(float f) {
    uint32_t u;
    asm("cvt.rna.tf32.f32 %0, %1;" : "=r"(u) : "f"(f));
    return u;
}

__global__ void gemm_mma_kernel(const float* __restrict__ W,
                                const float* __restrict__ bias,
                                float* __restrict__ out) {
    extern __shared__ uint32_t smem[];
    uint32_t* sA = smem;                 // 128 x SPITCH
    uint32_t* sW = smem + 128 * SPITCH;  // 128 x SPITCH
    const int t = threadIdx.x;
    const int row0 = blockIdx.x * 128;

    // stage W[n][k] (tf32) — 4096 float4 across 256 threads
    const float4* __restrict__ W4 = (const float4*)W;
    for (int idx = t; idx < 128 * 32; idx += 256) {
        int r = idx >> 5, q = idx & 31;
        float4 v = W4[r * 32 + q];
        uint32_t* d = &sW[r * SPITCH + q * 4];
        d[0] = f2tf32(v.x); d[1] = f2tf32(v.y);
        d[2] = f2tf32(v.z); d[3] = f2tf32(v.w);
    }
    // stage A tile (agg rows) as tf32
    const float4* __restrict__ A4 = (const float4*)g_agg;
    for (int idx = t; idx < 128 * 32; idx += 256) {
        int r = idx >> 5, q = idx & 31;
        int row = row0 + r;
        float4 v = (row < NUM_NODES) ? A4[row * 32 + q] : make_float4(0.f, 0.f, 0.f, 0.f);
        uint32_t* d = &sA[r * SPITCH + q * 4];
        d[0] = f2tf32(v.x); d[1] = f2tf32(v.y);
        d[2] = f2tf32(v.z); d[3] = f2tf32(v.w);
    }
    __syncthreads();

    const int warp = t >> 5, lane = t & 31;
    const int wm = warp >> 1;      // 0..3
    const int wn = warp & 1;       // 0..1
    const int gid = lane >> 2;     // 0..7
    const int tig = lane & 3;      // 0..3

    float c[2][8][4];
#pragma unroll
    for (int nt = 0; nt < 8; nt++) {
        int col0 = wn * 64 + nt * 8 + 2 * tig;
        float b0 = bias[col0], b1 = bias[col0 + 1];
#pragma unroll
        for (int mt = 0; mt < 2; mt++) {
            c[mt][nt][0] = b0; c[mt][nt][1] = b1;
            c[mt][nt][2] = b0; c[mt][nt][3] = b1;
        }
    }

#pragma unroll
    for (int kk = 0; kk < 16; kk++) {
        const int k0 = kk * 8;
        uint32_t a[2][4];
#pragma unroll
        for (int mt = 0; mt < 2; mt++) {
            int rb = wm * 32 + mt * 16;
            a[mt][0] = sA[(rb + gid) * SPITCH + k0 + tig];
            a[mt][1] = sA[(rb + gid + 8) * SPITCH + k0 + tig];
            a[mt][2] = sA[(rb + gid) * SPITCH + k0 + tig + 4];
            a[mt][3] = sA[(rb + gid + 8) * SPITCH + k0 + tig + 4];
        }
#pragma unroll
        for (int nt = 0; nt < 8; nt++) {
            int nb = wn * 64 + nt * 8;
            uint32_t bb0 = sW[(nb + gid) * SPITCH + k0 + tig];
            uint32_t bb1 = sW[(nb + gid) * SPITCH + k0 + tig + 4];
#pragma unroll
            for (int mt = 0; mt < 2; mt++) {
                asm volatile(
                    "mma.sync.aligned.m16n8k8.row.col.f32.tf32.tf32.f32 "
                    "{%0,%1,%2,%3}, {%4,%5,%6,%7}, {%8,%9}, {%0,%1,%2,%3};"
                    : "+f"(c[mt][nt][0]), "+f"(c[mt][nt][1]),
                      "+f"(c[mt][nt][2]), "+f"(c[mt][nt][3])
                    : "r"(a[mt][0]), "r"(a[mt][1]), "r"(a[mt][2]), "r"(a[mt][3]),
                      "r"(bb0), "r"(bb1));
            }
        }
    }

    // store: c0/c1 at (row, col..col+1), c2/c3 at (row+8, ..)
#pragma unroll
    for (int mt = 0; mt < 2; mt++) {
        int rb = wm * 32 + mt * 16;
        int row = row0 + rb + gid;
#pragma unroll
        for (int nt = 0; nt < 8; nt++) {
            int col = wn * 64 + nt * 8 + 2 * tig;
            if (row < NUM_NODES)
                *(float2*)&out[row * DIM + col] = make_float2(c[mt][nt][0], c[mt][nt][1]);
            if (row + 8 < NUM_NODES)
                *(float2*)&out[(row + 8) * DIM + col] = make_float2(c[mt][nt][2], c[mt][nt][3]);
        }
    }
}

// ---------------- launcher ----------------
extern "C" void kernel_launch(void* const* d_in, const int* in_sizes, int n_in,
                              void* d_out, int out_size) {
    const float* x  = (const float*)d_in[0];
    const int*   ei = (const int*)d_in[1];     // edge_index: int32 (JAX x64 disabled)
    const float* ew = (const float*)d_in[2];
    const float* W  = (const float*)d_in[3];
    const float* b  = (const float*)d_in[4];
    float* out = (float*)d_out;

    (void)in_sizes; (void)n_in; (void)out_size;

    const int gemm_smem = 2 * 128 * SPITCH * 4;   // 135168 bytes
    cudaFuncSetAttribute(gemm_mma_kernel,
                         cudaFuncAttributeMaxDynamicSharedMemorySize, gemm_smem);

    init_kernel<<<(NUM_NODES + 255) / 256, 256>>>();
    edge_pass_kernel<<<(NUM_EDGES + 255) / 256, 256>>>(ei, ew);
    partial_dinv_kernel<<<SCAN_NB, SCAN_BLK>>>();
    bscan_kernel<<<1, 128>>>();
    offsets_kernel<<<SCAN_NB, SCAN_BLK>>>();
    scatter_kernel<<<(NUM_EDGES + 255) / 256, 256>>>(ei, ew);
    agg_kernel<<<(NUM_NODES * 32 + 255) / 256, 256>>>(x);
    gemm_mma_kernel<<<(NUM_NODES + 127) / 128, 256, gemm_smem>>>(W, b, out);
}

// round 5
// speedup vs baseline: 1.6619x; 1.0688x over previous
#include <cuda_runtime.h>
#include <cuda_bf16.h>
#include <cstdint>

#define NUM_NODES 50000
#define NUM_EDGES 600000
#define DIM 128

#define SCAN_BLK 512
#define SCAN_NB  ((NUM_NODES + SCAN_BLK - 1) / SCAN_BLK)   // 98

// ---------------- scratch (static __device__ globals; no allocation) ----------------
__device__ float g_deg[NUM_NODES];
__device__ float g_dinv[NUM_NODES];
__device__ int   g_count[NUM_NODES];
__device__ int   g_offset[NUM_NODES + 1];
__device__ __align__(16) int2 g_edge[NUM_EDGES];   // {src, w_norm bits}, tgt-sorted
__device__ int   g_bsum[SCAN_NB];

// ---------------- kernel 1: init ----------------
__global__ void init_kernel() {
    int i = blockIdx.x * blockDim.x + threadIdx.x;
    if (i < NUM_NODES) {
        g_deg[i] = 1.0f;     // self-loop weight
        g_count[i] = 0;
    }
}

// ---------------- kernel 2: degree + tgt histogram (edge_index is INT32) ----------------
__global__ void edge_pass_kernel(const int* __restrict__ eidx,
                                 const float* __restrict__ ew) {
    int e = blockIdx.x * blockDim.x + threadIdx.x;
    if (e >= NUM_EDGES) return;
    int src = eidx[e];
    int tgt = eidx[NUM_EDGES + e];
    if ((unsigned)src < NUM_NODES) atomicAdd(&g_deg[src], ew[e]);
    if ((unsigned)tgt < NUM_NODES) atomicAdd(&g_count[tgt], 1);
}

// ---------------- kernel 3: per-block count sums + dinv (fused) ----------------
__global__ void partial_dinv_kernel() {
    int i = blockIdx.x * SCAN_BLK + threadIdx.x;
    int lane = threadIdx.x & 31, wid = threadIdx.x >> 5;
    int c = (i < NUM_NODES) ? g_count[i] : 0;
    if (i < NUM_NODES) g_dinv[i] = rsqrtf(g_deg[i]);

    int s = c;
#pragma unroll
    for (int d = 16; d > 0; d >>= 1) s += __shfl_down_sync(0xFFFFFFFFu, s, d);
    __shared__ int ws[SCAN_BLK / 32];
    if (lane == 0) ws[wid] = s;
    __syncthreads();
    if (threadIdx.x == 0) {
        int tot = 0;
#pragma unroll
        for (int w = 0; w < SCAN_BLK / 32; w++) tot += ws[w];
        g_bsum[blockIdx.x] = tot;
    }
}

// ---------------- kernel 4: offsets (block-prefix reduction inlined) ----------------
__global__ void offsets_kernel() {
    const int t = threadIdx.x;
    const int lane = t & 31, wid = t >> 5;
    __shared__ int red[SCAN_BLK / 32];
    __shared__ int ws[SCAN_BLK / 32];
    __shared__ int s_bpre;

    // inline reduction: sum of g_bsum[0 .. blockIdx.x-1]
    int bv = (t < blockIdx.x) ? g_bsum[t] : 0;   // blockIdx.x <= 97 < 512
    int br = bv;
#pragma unroll
    for (int d = 16; d > 0; d >>= 1) br += __shfl_down_sync(0xFFFFFFFFu, br, d);
    if (lane == 0) red[wid] = br;
    __syncthreads();
    if (t == 0) {
        int a = 0;
#pragma unroll
        for (int w = 0; w < SCAN_BLK / 32; w++) a += red[w];
        s_bpre = a;
    }

    int i = blockIdx.x * SCAN_BLK + t;
    int v = (i < NUM_NODES) ? g_count[i] : 0;
    int s = v;
#pragma unroll
    for (int d = 1; d < 32; d <<= 1) {
        int tmp = __shfl_up_sync(0xFFFFFFFFu, s, d);
        if (lane >= d) s += tmp;
    }
    if (lane == 31) ws[wid] = s;
    __syncthreads();
    if (wid == 0) {
        const int n = SCAN_BLK / 32;
        int wv = (lane < n) ? ws[lane] : 0;
        int t2 = wv;
#pragma unroll
        for (int d = 1; d < 32; d <<= 1) {
            int tmp = __shfl_up_sync(0xFFFFFFFFu, t2, d);
            if (lane >= d) t2 += tmp;
        }
        if (lane < n) ws[lane] = t2 - wv;   // exclusive warp prefix
    }
    __syncthreads();
    if (i < NUM_NODES) g_offset[i + 1] = s_bpre + ws[wid] + s;
    if (i == 0) g_offset[0] = 0;
}

// ---------------- kernel 5: scatter (atomicSub on counts; packed int2 record) ----------------
__global__ void scatter_kernel(const int* __restrict__ eidx,
                               const float* __restrict__ ew) {
    int e = blockIdx.x * blockDim.x + threadIdx.x;
    if (e >= NUM_EDGES) return;
    int src = eidx[e];
    int tgt = eidx[NUM_EDGES + e];
    if ((unsigned)src >= NUM_NODES || (unsigned)tgt >= NUM_NODES) return;
    int pos = g_offset[tgt] + atomicSub(&g_count[tgt], 1) - 1;
    float w = ew[e] * g_dinv[src] * g_dinv[tgt];
    g_edge[pos] = make_int2(src, __float_as_int(w));
}

// ---------------- kernel 6: fused aggregation + tf32 tensor-core GEMM ----------------
// 512 threads (16 warps). Tile: 128 nodes x 128 out-cols, K=128.
// Phase A: warp w aggregates nodes [w*8, w*8+8) into smem A-tile (tf32).
// Phase B: warp (wm=w>>2, wn=w&3) computes m32 x n32 with mma.m16n8k8 tf32.
#define SPITCH 132   // smem row pitch in words (bank-conflict-free fragment loads)
#define FB_THREADS 512

__device__ __forceinline__ uint32_t f2tf32(float f) {
    uint32_t u;
    asm("cvt.rna.tf32.f32 %0, %1;" : "=r"(u) : "f"(f));
    return u;
}

__global__ void fused_agg_gemm_kernel(const float* __restrict__ x,
                                      const float* __restrict__ W,
                                      const float* __restrict__ bias,
                                      float* __restrict__ out) {
    extern __shared__ uint32_t smem[];
    uint32_t* sA = smem;                 // 128 x SPITCH
    uint32_t* sW = smem + 128 * SPITCH;  // 128 x SPITCH
    const int t = threadIdx.x;
    const int warp = t >> 5, lane = t & 31;
    const int row0 = blockIdx.x * 128;

    // ---- stage W[n][k] as tf32 ----
    const float4* __restrict__ W4 = (const float4*)W;
    for (int idx = t; idx < 128 * 32; idx += FB_THREADS) {
        int r = idx >> 5, q = idx & 31;
        float4 v = W4[r * 32 + q];
        uint4 p = make_uint4(f2tf32(v.x), f2tf32(v.y), f2tf32(v.z), f2tf32(v.w));
        *(uint4*)&sW[r * SPITCH + q * 4] = p;
    }

    // ---- phase A: aggregate 8 nodes per warp into sA ----
    const float4* __restrict__ x4 = (const float4*)x;
#pragma unroll
    for (int i = 0; i < 8; i++) {
        const int r = warp * 8 + i;
        const int node = row0 + r;
        float4 acc = make_float4(0.f, 0.f, 0.f, 0.f);
        if (node < NUM_NODES) {
            float di = g_dinv[node];
            float wl = di * di;                       // self-loop weight
            float4 xv = __ldg(&x4[node * 32 + lane]);
            acc.x = wl * xv.x; acc.y = wl * xv.y;
            acc.z = wl * xv.z; acc.w = wl * xv.w;
            const int beg = __ldg(&g_offset[node]);
            const int end = __ldg(&g_offset[node + 1]);
#pragma unroll 4
            for (int e = beg; e < end; e++) {
                int2 rec = g_edge[e];                 // broadcast across warp
                float w = __int_as_float(rec.y);
                float4 v = __ldg(&x4[rec.x * 32 + lane]);
                acc.x += w * v.x; acc.y += w * v.y;
                acc.z += w * v.z; acc.w += w * v.w;
            }
        }
        uint4 p = make_uint4(f2tf32(acc.x), f2tf32(acc.y), f2tf32(acc.z), f2tf32(acc.w));
        *(uint4*)&sA[r * SPITCH + lane * 4] = p;
    }
    __syncthreads();

    // ---- phase B: MMA. warp grid 4x4, each warp m32 x n32 ----
    const int wm = warp >> 2;      // 0..3
    const int wn = warp & 3;       // 0..3
    const int gid = lane >> 2;     // 0..7
    const int tig = lane & 3;      // 0..3

    float c[2][4][4];
#pragma unroll
    for (int nt = 0; nt < 4; nt++) {
        int col0 = wn * 32 + nt * 8 + 2 * tig;
        float b0 = bias[col0], b1 = bias[col0 + 1];
#pragma unroll
        for (int mt = 0; mt < 2; mt++) {
            c[mt][nt][0] = b0; c[mt][nt][1] = b1;
            c[mt][nt][2] = b0; c[mt][nt][3] = b1;
        }
    }

#pragma unroll
    for (int kk = 0; kk < 16; kk++) {
        const int k0 = kk * 8;
        uint32_t a[2][4];
#pragma unroll
        for (int mt = 0; mt < 2; mt++) {
            int rb = wm * 32 + mt * 16;
            a[mt][0] = sA[(rb + gid) * SPITCH + k0 + tig];
            a[mt][1] = sA[(rb + gid + 8) * SPITCH + k0 + tig];
            a[mt][2] = sA[(rb + gid) * SPITCH + k0 + tig + 4];
            a[mt][3] = sA[(rb + gid + 8) * SPITCH + k0 + tig + 4];
        }
#pragma unroll
        for (int nt = 0; nt < 4; nt++) {
            int nb = wn * 32 + nt * 8;
            uint32_t bb0 = sW[(nb + gid) * SPITCH + k0 + tig];
            uint32_t bb1 = sW[(nb + gid) * SPITCH + k0 + tig + 4];
#pragma unroll
            for (int mt = 0; mt < 2; mt++) {
                asm volatile(
                    "mma.sync.aligned.m16n8k8.row.col.f32.tf32.tf32.f32 "
                    "{%0,%1,%2,%3}, {%4,%5,%6,%7}, {%8,%9}, {%0,%1,%2,%3};"
                    : "+f"(c[mt][nt][0]), "+f"(c[mt][nt][1]),
                      "+f"(c[mt][nt][2]), "+f"(c[mt][nt][3])
                    : "r"(a[mt][0]), "r"(a[mt][1]), "r"(a[mt][2]), "r"(a[mt][3]),
                      "r"(bb0), "r"(bb1));
            }
        }
    }

    // ---- store ----
#pragma unroll
    for (int mt = 0; mt < 2; mt++) {
        int rb = wm * 32 + mt * 16;
        int row = row0 + rb + gid;
#pragma unroll
        for (int nt = 0; nt < 4; nt++) {
            int col = wn * 32 + nt * 8 + 2 * tig;
            if (row < NUM_NODES)
                *(float2*)&out[row * DIM + col] = make_float2(c[mt][nt][0], c[mt][nt][1]);
            if (row + 8 < NUM_NODES)
                *(float2*)&out[(row + 8) * DIM + col] = make_float2(c[mt][nt][2], c[mt][nt][3]);
        }
    }
}

// ---------------- launcher ----------------
extern "C" void kernel_launch(void* const* d_in, const int* in_sizes, int n_in,
                              void* d_out, int out_size) {
    const float* x  = (const float*)d_in[0];
    const int*   ei = (const int*)d_in[1];     // edge_index: int32 (JAX x64 disabled)
    const float* ew = (const float*)d_in[2];
    const float* W  = (const float*)d_in[3];
    const float* b  = (const float*)d_in[4];
    float* out = (float*)d_out;

    (void)in_sizes; (void)n_in; (void)out_size;

    const int fused_smem = 2 * 128 * SPITCH * 4;   // 135168 bytes
    cudaFuncSetAttribute(fused_agg_gemm_kernel,
                         cudaFuncAttributeMaxDynamicSharedMemorySize, fused_smem);

    init_kernel<<<(NUM_NODES + 255) / 256, 256>>>();
    edge_pass_kernel<<<(NUM_EDGES + 255) / 256, 256>>>(ei, ew);
    partial_dinv_kernel<<<SCAN_NB, SCAN_BLK>>>();
    offsets_kernel<<<SCAN_NB, SCAN_BLK>>>();
    scatter_kernel<<<(NUM_EDGES + 255) / 256, 256>>>(ei, ew);
    fused_agg_gemm_kernel<<<(NUM_NODES + 127) / 128, FB_THREADS, fused_smem>>>(x, W, b, out);
}

// round 12
// speedup vs baseline: 1.6659x; 1.0024x over previous
#include <cuda_runtime.h>
#include <cuda_bf16.h>
#include <cstdint>

#define NUM_NODES 50000
#define NUM_EDGES 600000
#define DIM 128

#define SCAN_BLK 512
#define SCAN_NB  ((NUM_NODES + SCAN_BLK - 1) / SCAN_BLK)   // 98
#define NTILES   ((NUM_NODES + 127) / 128)                 // 391
#define FGRID    148

// ---------------- scratch (static __device__ globals; no allocation) ----------------
__device__ float g_deg[NUM_NODES];
__device__ float g_dinv[NUM_NODES];
__device__ int   g_count[NUM_NODES];
__device__ int   g_offset[NUM_NODES + 1];
__device__ __align__(16) int2 g_edge[NUM_EDGES];   // {src, w_norm bits}, tgt-sorted
__device__ int   g_bsum[SCAN_NB];

// ---------------- kernel 1: init ----------------
__global__ void init_kernel() {
    int i = blockIdx.x * blockDim.x + threadIdx.x;
    if (i < NUM_NODES) {
        g_deg[i] = 1.0f;     // self-loop weight
        g_count[i] = 0;
    }
}

// ---------------- kernel 2: degree + tgt histogram, 2 edges/thread ----------------
__global__ void edge_pass_kernel(const int* __restrict__ eidx,
                                 const float* __restrict__ ew) {
    int e = 2 * (blockIdx.x * blockDim.x + threadIdx.x);
    if (e >= NUM_EDGES) return;
    int2 src2 = *(const int2*)&eidx[e];
    int2 tgt2 = *(const int2*)&eidx[NUM_EDGES + e];
    float2 w2 = *(const float2*)&ew[e];
    if ((unsigned)src2.x < NUM_NODES) atomicAdd(&g_deg[src2.x], w2.x);
    if ((unsigned)tgt2.x < NUM_NODES) atomicAdd(&g_count[tgt2.x], 1);
    if ((unsigned)src2.y < NUM_NODES) atomicAdd(&g_deg[src2.y], w2.y);
    if ((unsigned)tgt2.y < NUM_NODES) atomicAdd(&g_count[tgt2.y], 1);
}

// ---------------- kernel 3: per-block count sums + dinv (fused) ----------------
__global__ void partial_dinv_kernel() {
    int i = blockIdx.x * SCAN_BLK + threadIdx.x;
    int lane = threadIdx.x & 31, wid = threadIdx.x >> 5;
    int c = (i < NUM_NODES) ? g_count[i] : 0;
    if (i < NUM_NODES) g_dinv[i] = rsqrtf(g_deg[i]);

    int s = c;
#pragma unroll
    for (int d = 16; d > 0; d >>= 1) s += __shfl_down_sync(0xFFFFFFFFu, s, d);
    __shared__ int ws[SCAN_BLK / 32];
    if (lane == 0) ws[wid] = s;
    __syncthreads();
    if (threadIdx.x == 0) {
        int tot = 0;
#pragma unroll
        for (int w = 0; w < SCAN_BLK / 32; w++) tot += ws[w];
        g_bsum[blockIdx.x] = tot;
    }
}

// ---------------- kernel 4: offsets (block-prefix reduction inlined) ----------------
__global__ void offsets_kernel() {
    const int t = threadIdx.x;
    const int lane = t & 31, wid = t >> 5;
    __shared__ int red[SCAN_BLK / 32];
    __shared__ int ws[SCAN_BLK / 32];
    __shared__ int s_bpre;

    int bv = (t < blockIdx.x) ? g_bsum[t] : 0;   // blockIdx.x <= 97 < 512
    int br = bv;
#pragma unroll
    for (int d = 16; d > 0; d >>= 1) br += __shfl_down_sync(0xFFFFFFFFu, br, d);
    if (lane == 0) red[wid] = br;
    __syncthreads();
    if (t == 0) {
        int a = 0;
#pragma unroll
        for (int w = 0; w < SCAN_BLK / 32; w++) a += red[w];
        s_bpre = a;
    }

    int i = blockIdx.x * SCAN_BLK + t;
    int v = (i < NUM_NODES) ? g_count[i] : 0;
    int s = v;
#pragma unroll
    for (int d = 1; d < 32; d <<= 1) {
        int tmp = __shfl_up_sync(0xFFFFFFFFu, s, d);
        if (lane >= d) s += tmp;
    }
    if (lane == 31) ws[wid] = s;
    __syncthreads();
    if (wid == 0) {
        const int n = SCAN_BLK / 32;
        int wv = (lane < n) ? ws[lane] : 0;
        int t2 = wv;
#pragma unroll
        for (int d = 1; d < 32; d <<= 1) {
            int tmp = __shfl_up_sync(0xFFFFFFFFu, t2, d);
            if (lane >= d) t2 += tmp;
        }
        if (lane < n) ws[lane] = t2 - wv;   // exclusive warp prefix
    }
    __syncthreads();
    if (i < NUM_NODES) g_offset[i + 1] = s_bpre + ws[wid] + s;
    if (i == 0) g_offset[0] = 0;
}

// ---------------- kernel 5: scatter, 2 edges/thread ----------------
__global__ void scatter_kernel(const int* __restrict__ eidx,
                               const float* __restrict__ ew) {
    int e = 2 * (blockIdx.x * blockDim.x + threadIdx.x);
    if (e >= NUM_EDGES) return;
    int2 src2 = *(const int2*)&eidx[e];
    int2 tgt2 = *(const int2*)&eidx[NUM_EDGES + e];
    float2 w2 = *(const float2*)&ew[e];

    if ((unsigned)src2.x < NUM_NODES && (unsigned)tgt2.x < NUM_NODES) {
        int pos = g_offset[tgt2.x] + atomicSub(&g_count[tgt2.x], 1) - 1;
        float w = w2.x * g_dinv[src2.x] * g_dinv[tgt2.x];
        g_edge[pos] = make_int2(src2.x, __float_as_int(w));
    }
    if ((unsigned)src2.y < NUM_NODES && (unsigned)tgt2.y < NUM_NODES) {
        int pos = g_offset[tgt2.y] + atomicSub(&g_count[tgt2.y], 1) - 1;
        float w = w2.y * g_dinv[src2.y] * g_dinv[tgt2.y];
        g_edge[pos] = make_int2(src2.y, __float_as_int(w));
    }
}

// ---------------- kernel 6: persistent fused aggregation + tf32 MMA GEMM ----------------
// grid=148 blocks x 512 threads (16 warps). Each block loops tiles (stride 148).
// W staged once per block. Per tile: phase A aggregates 128 nodes into tf32 sA,
// phase B: 4x4 warp grid, each warp m32 x n32 with mma.m16n8k8 tf32.
#define SPITCH 132
#define FB_THREADS 512

__device__ __forceinline__ uint32_t f2tf32(float f) {
    uint32_t u;
    asm("cvt.rna.tf32.f32 %0, %1;" : "=r"(u) : "f"(f));
    return u;
}

__global__ __launch_bounds__(FB_THREADS, 1)
void fused_agg_gemm_kernel(const float* __restrict__ x,
                           const float* __restrict__ W,
                           const float* __restrict__ bias,
                           float* __restrict__ out) {
    extern __shared__ uint32_t smem[];
    uint32_t* sA = smem;                 // 128 x SPITCH
    uint32_t* sW = smem + 128 * SPITCH;  // 128 x SPITCH
    const int t = threadIdx.x;
    const int warp = t >> 5, lane = t & 31;

    // ---- stage W[n][k] as tf32 (once per block) ----
    const float4* __restrict__ W4 = (const float4*)W;
    for (int idx = t; idx < 128 * 32; idx += FB_THREADS) {
        int r = idx >> 5, q = idx & 31;
        float4 v = W4[r * 32 + q];
        uint4 p = make_uint4(f2tf32(v.x), f2tf32(v.y), f2tf32(v.z), f2tf32(v.w));
        *(uint4*)&sW[r * SPITCH + q * 4] = p;
    }

    const int wm = warp >> 2, wn = warp & 3;
    const int gid = lane >> 2, tig = lane & 3;
    const float4* __restrict__ x4 = (const float4*)x;

    // bias fragment (invariant across tiles)
    float bfrag[4][2];
#pragma unroll
    for (int nt = 0; nt < 4; nt++) {
        int col0 = wn * 32 + nt * 8 + 2 * tig;
        bfrag[nt][0] = bias[col0];
        bfrag[nt][1] = bias[col0 + 1];
    }
    __syncthreads();

    for (int tile = blockIdx.x; tile < NTILES; tile += FGRID) {
        const int row0 = tile * 128;

        // ---- phase A: aggregate 8 nodes per warp into sA ----
#pragma unroll
        for (int i = 0; i < 8; i++) {
            const int r = warp * 8 + i;
            const int node = row0 + r;
            float4 acc = make_float4(0.f, 0.f, 0.f, 0.f);
            if (node < NUM_NODES) {
                float di = g_dinv[node];
                float wl = di * di;                       // self-loop weight
                float4 xv = __ldg(&x4[node * 32 + lane]);
                acc.x = wl * xv.x; acc.y = wl * xv.y;
                acc.z = wl * xv.z; acc.w = wl * xv.w;
                const int beg = __ldg(&g_offset[node]);
                const int end = __ldg(&g_offset[node + 1]);
#pragma unroll 8
                for (int e = beg; e < end; e++) {
                    int2 rec = g_edge[e];                 // broadcast across warp
                    float w = __int_as_float(rec.y);
                    float4 v = __ldg(&x4[rec.x * 32 + lane]);
                    acc.x += w * v.x; acc.y += w * v.y;
                    acc.z += w * v.z; acc.w += w * v.w;
                }
            }
            uint4 p = make_uint4(f2tf32(acc.x), f2tf32(acc.y), f2tf32(acc.z), f2tf32(acc.w));
            *(uint4*)&sA[r * SPITCH + lane * 4] = p;
        }
        __syncthreads();

        // ---- phase B: MMA ----
        float c[2][4][4];
#pragma unroll
        for (int nt = 0; nt < 4; nt++) {
#pragma unroll
            for (int mt = 0; mt < 2; mt++) {
                c[mt][nt][0] = bfrag[nt][0]; c[mt][nt][1] = bfrag[nt][1];
                c[mt][nt][2] = bfrag[nt][0]; c[mt][nt][3] = bfrag[nt][1];
            }
        }

#pragma unroll
        for (int kk = 0; kk < 16; kk++) {
            const int k0 = kk * 8;
            uint32_t a[2][4];
#pragma unroll
            for (int mt = 0; mt < 2; mt++) {
                int rb = wm * 32 + mt * 16;
                a[mt][0] = sA[(rb + gid) * SPITCH + k0 + tig];
                a[mt][1] = sA[(rb + gid + 8) * SPITCH + k0 + tig];
                a[mt][2] = sA[(rb + gid) * SPITCH + k0 + tig + 4];
                a[mt][3] = sA[(rb + gid + 8) * SPITCH + k0 + tig + 4];
            }
#pragma unroll
            for (int nt = 0; nt < 4; nt++) {
                int nb = wn * 32 + nt * 8;
                uint32_t bb0 = sW[(nb + gid) * SPITCH + k0 + tig];
                uint32_t bb1 = sW[(nb + gid) * SPITCH + k0 + tig + 4];
#pragma unroll
                for (int mt = 0; mt < 2; mt++) {
                    asm volatile(
                        "mma.sync.aligned.m16n8k8.row.col.f32.tf32.tf32.f32 "
                        "{%0,%1,%2,%3}, {%4,%5,%6,%7}, {%8,%9}, {%0,%1,%2,%3};"
                        : "+f"(c[mt][nt][0]), "+f"(c[mt][nt][1]),
                          "+f"(c[mt][nt][2]), "+f"(c[mt][nt][3])
                        : "r"(a[mt][0]), "r"(a[mt][1]), "r"(a[mt][2]), "r"(a[mt][3]),
                          "r"(bb0), "r"(bb1));
                }
            }
        }

        // ---- store ----
#pragma unroll
        for (int mt = 0; mt < 2; mt++) {
            int rb = wm * 32 + mt * 16;
            int row = row0 + rb + gid;
#pragma unroll
            for (int nt = 0; nt < 4; nt++) {
                int col = wn * 32 + nt * 8 + 2 * tig;
                if (row < NUM_NODES)
                    *(float2*)&out[row * DIM + col] = make_float2(c[mt][nt][0], c[mt][nt][1]);
                if (row + 8 < NUM_NODES)
                    *(float2*)&out[(row + 8) * DIM + col] = make_float2(c[mt][nt][2], c[mt][nt][3]);
            }
        }
        __syncthreads();   // protect sA reuse next tile
    }
}

// ---------------- launcher ----------------
extern "C" void kernel_launch(void* const* d_in, const int* in_sizes, int n_in,
                              void* d_out, int out_size) {
    const float* x  = (const float*)d_in[0];
    const int*   ei = (const int*)d_in[1];     // edge_index: int32 (JAX x64 disabled)
    const float* ew = (const float*)d_in[2];
    const float* W  = (const float*)d_in[3];
    const float* b  = (const float*)d_in[4];
    float* out = (float*)d_out;

    (void)in_sizes; (void)n_in; (void)out_size;

    const int fused_smem = 2 * 128 * SPITCH * 4;   // 135168 bytes
    cudaFuncSetAttribute(fused_agg_gemm_kernel,
                         cudaFuncAttributeMaxDynamicSharedMemorySize, fused_smem);

    init_kernel<<<(NUM_NODES + 255) / 256, 256>>>();
    edge_pass_kernel<<<(NUM_EDGES / 2 + 255) / 256, 256>>>(ei, ew);
    partial_dinv_kernel<<<SCAN_NB, SCAN_BLK>>>();
    offsets_kernel<<<SCAN_NB, SCAN_BLK>>>();
    scatter_kernel<<<(NUM_EDGES / 2 + 255) / 256, 256>>>(ei, ew);
    fused_agg_gemm_kernel<<<FGRID, FB_THREADS, fused_smem>>>(x, W, b, out);
}